// round 8
// baseline (speedup 1.0000x reference)
#include <cuda_runtime.h>
#include <cstdint>

#define BB 64
#define HH 1024
#define SS 2048
#define LL 15
#define BKK 16
#define BNN 128

typedef unsigned long long ull;

// ---------------- scratch (static device globals; no allocation) ------------
// Activations K-major plain float: A[k*64 + b]
__device__ float g_T[3 * HH * BB];      // tanh prep outputs
__device__ float g_bcat[3 * HH];        // concat(b_cls,b_e1,b_e2)
__device__ float g_H3[3 * HH * BB];     // GEMM1 output [3H][B]
__device__ float g_h1[HH * BB];         // GEMM2 output [H][B]
__device__ float g_h2[HH * BB];         // GEMM3 output [H][B]
__device__ float g_P[48 * HH * BB];     // split-K partials [q][n][b]

// ---------------- f32x2 packed helpers --------------------------------------
__device__ __forceinline__ ull pack2(float x) {
    ull r; unsigned xi = __float_as_uint(x);
    asm("mov.b64 %0, {%1, %1};" : "=l"(r) : "r"(xi));
    return r;
}
__device__ __forceinline__ void ffma2(ull& acc, ull a, ull b) {
    asm("fma.rn.f32x2 %0, %1, %2, %3;" : "=l"(acc) : "l"(a), "l"(b), "l"(acc));
}
__device__ __forceinline__ float2 unpack2(ull v) {
    unsigned lo, hi;
    asm("mov.b64 {%0, %1}, %2;" : "=r"(lo), "=r"(hi) : "l"(v));
    float2 f; f.x = __uint_as_float(lo); f.y = __uint_as_float(hi);
    return f;
}

// ---------------- cp.async helpers ------------------------------------------
__device__ __forceinline__ void cp16(void* s, const void* g) {
    unsigned ss = (unsigned)__cvta_generic_to_shared(s);
    asm volatile("cp.async.cg.shared.global [%0], [%1], 16;" :: "r"(ss), "l"(g));
}
#define CP_COMMIT asm volatile("cp.async.commit_group;")
#define CP_WAIT0  asm volatile("cp.async.wait_group 0;")

// ---------------- prep: span means + tanh + bias concat ---------------------
__global__ void prep_kernel(const float* __restrict__ x,
                            const int* __restrict__ eidx,
                            const float* __restrict__ b_cls,
                            const float* __restrict__ b_e1,
                            const float* __restrict__ b_e2) {
    int b = blockIdx.x;
    int tid = threadIdx.x;  // 256
    int h = blockIdx.y * 256 + tid;

    if (blockIdx.y == 0 && b < 12) {
        int gidx = b * 256 + tid;
        if (gidx < HH)          g_bcat[gidx] = b_cls[gidx];
        else if (gidx < 2 * HH) g_bcat[gidx] = b_e1[gidx - HH];
        else                    g_bcat[gidx] = b_e2[gidx - 2 * HH];
    }

    int s1 = eidx[b * 4 + 0], e1 = eidx[b * 4 + 1];
    int s2 = eidx[b * 4 + 2], e2 = eidx[b * 4 + 3];
    float c1 = 1.0f / (float)max(e1 - s1, 1);
    float c2 = 1.0f / (float)max(e2 - s2, 1);
    const float* xb = x + (size_t)b * SS * HH;

    float t0 = tanhf(xb[h]);
    float a1 = 0.f;
    for (int p = s1; p < e1; ++p) a1 += xb[(size_t)p * HH + h];
    float a2 = 0.f;
    for (int p = s2; p < e2; ++p) a2 += xb[(size_t)p * HH + h];
    g_T[(size_t)(0 * HH + h) * BB + b] = t0;
    g_T[(size_t)(1 * HH + h) * BB + b] = tanhf(a1 * c1);
    g_T[(size_t)(2 * HH + h) * BB + b] = tanhf(a2 * c2);
}

// ---------------- split-K skinny GEMM (M=64): X via LDG, W via smem ----------
// X K-major [K][64] float, read directly from global (L1/L2 cached, no crossbar).
// W double-buffered in smem, conflict-free LDS.128 (lane-stride 16B).
// Block tile 64(b) x 128(n), BK=16, 128 threads, thread tile 8b x 8n.
__global__ __launch_bounds__(128)
void gemm_split(int xsel,                    // 0: g_T, 1: g_H3, 2: g_h1
                const float* __restrict__ W0,
                const float* __restrict__ We1,
                const float* __restrict__ We2,
                int seg,                     // 0: single weight; else cols/segment
                int Ntot, int ldw, int kchunk) {
    const float* X = (xsel == 0) ? g_T : (xsel == 1) ? g_H3 : g_h1;
    int n0 = blockIdx.x * BNN;
    const float* W = W0;
    int ncol = n0;
    if (seg) {
        int which = n0 / seg;
        W = (which == 0) ? W0 : (which == 1 ? We1 : We2);
        ncol = n0 - which * seg;
        X += (size_t)which * HH * BB;   // segment rows
    }
    int kbeg = blockIdx.y * kchunk;
    int ntiles = kchunk / BKK;

    __shared__ float Ws[2][BKK][BNN];   // 2 x 8KB

    int tid = threadIdx.x;
    int tn = tid & 15;   // n group 0..15
    int tb = tid >> 4;   // b group 0..7 (8 rows each)

    const float* Xt = X + tb * 8;       // this thread's b-slice

    ull acc[8][4];
#pragma unroll
    for (int i = 0; i < 8; i++)
#pragma unroll
        for (int j = 0; j < 4; j++) acc[i][j] = 0ULL;

    // --- W staging: 8KB tile, 4 cp16/thread
    auto stage = [&](int s, int k0) {
#pragma unroll
        for (int i = 0; i < 4; i++) {
            int p = tid + 128 * i;                 // 0..511
            int r = p >> 5, c = (p & 31) * 4;      // 16 rows x 32 chunks of 4 floats
            cp16(&Ws[s][r][c], W + (size_t)(k0 + r) * ldw + ncol + c);
        }
        CP_COMMIT;
    };

    stage(0, kbeg);

    for (int t = 0; t < ntiles; t++) {
        int s = t & 1;
        CP_WAIT0;                 // W tile t ready
        __syncthreads();          // all warps done reading buffer s (tile t-2)
        if (t + 1 < ntiles) stage(s ^ 1, kbeg + (t + 1) * BKK);  // overlap prefetch
        int k0 = kbeg + t * BKK;

#pragma unroll
        for (int kk = 0; kk < BKK; ++kk) {
            // X via LDG (L1-cached, CTA-wide reuse across tn)
            const float4* xp = (const float4*)(Xt + (size_t)(k0 + kk) * BB);
            float4 xa = __ldg(xp);
            float4 xc = __ldg(xp + 1);
            ull x2[8];
            x2[0] = pack2(xa.x); x2[1] = pack2(xa.y);
            x2[2] = pack2(xa.z); x2[3] = pack2(xa.w);
            x2[4] = pack2(xc.x); x2[5] = pack2(xc.y);
            x2[6] = pack2(xc.z); x2[7] = pack2(xc.w);
            // conflict-free W: lane-stride 16B within each 128B phase
            ulonglong2 wv0 = *(const ulonglong2*)&Ws[s][kk][tn * 4];       // n = tn*4..+3
            ulonglong2 wv1 = *(const ulonglong2*)&Ws[s][kk][64 + tn * 4];  // n = 64+tn*4..+3
            ull w2[4]; w2[0] = wv0.x; w2[1] = wv0.y; w2[2] = wv1.x; w2[3] = wv1.y;
#pragma unroll
            for (int i = 0; i < 8; i++)
#pragma unroll
                for (int j = 0; j < 4; j++) ffma2(acc[i][j], x2[i], w2[j]);
        }
    }

    // --- write partials: P[(q*Ntot + n)*64 + b]
    float* pbase = g_P + ((size_t)blockIdx.y * Ntot + n0) * BB + tb * 8;
#pragma unroll
    for (int j = 0; j < 4; j++) {
        int nrow = (j < 2) ? (tn * 4 + 2 * j) : (64 + tn * 4 + 2 * (j - 2));
        float2 f0 = unpack2(acc[0][j]), f1 = unpack2(acc[1][j]);
        float2 f2 = unpack2(acc[2][j]), f3 = unpack2(acc[3][j]);
        float2 f4 = unpack2(acc[4][j]), f5 = unpack2(acc[5][j]);
        float2 f6 = unpack2(acc[6][j]), f7 = unpack2(acc[7][j]);
        float* r0 = pbase + (size_t)nrow * BB;
        *(float4*)r0       = make_float4(f0.x, f1.x, f2.x, f3.x);
        *(float4*)(r0 + 4) = make_float4(f4.x, f5.x, f6.x, f7.x);
        float* r1 = pbase + (size_t)(nrow + 1) * BB;
        *(float4*)r1       = make_float4(f0.y, f1.y, f2.y, f3.y);
        *(float4*)(r1 + 4) = make_float4(f4.y, f5.y, f6.y, f7.y);
    }
}

// ---------------- reduce split-K partials + bias (layout [n][b]) -------------
__global__ __launch_bounds__(512)
void reduce_bias(const float* __restrict__ bias,  // nullptr -> g_bcat
                 int ysel,                        // 0:g_H3 1:g_h1 2:g_h2
                 int Ntot, int ks) {
    float* Y = (ysel == 0) ? g_H3 : (ysel == 1) ? g_h1 : g_h2;
    const float* bp = bias ? bias : g_bcat;
    int idx = blockIdx.x * 512 + threadIdx.x;     // float4 index over Ntot*BB
    int total = Ntot * BB / 4;
    if (idx >= total) return;
    const float4* P4 = (const float4*)g_P;
    float4 s = __ldg(&P4[idx]);
#pragma unroll 4
    for (int q = 1; q < ks; q++) {
        float4 v = __ldg(&P4[(size_t)q * total + idx]);
        s.x += v.x; s.y += v.y; s.z += v.z; s.w += v.w;
    }
    int n = idx >> 4;            // 16 float4 per n row (BB=64)
    float bv = bp[n];
    s.x += bv; s.y += bv; s.z += bv; s.w += bv;
    ((float4*)Y)[idx] = s;
}

// ---------------- tiny output GEMM: h2[n][b] x Wout[1024,15] -----------------
__global__ void out_gemm(const float* __restrict__ Wout,
                         const float* __restrict__ bout,
                         float* __restrict__ out) {
    int n = blockIdx.x;   // 0..14
    int b = blockIdx.y;   // 0..63
    float s = 0.f;
    for (int k = threadIdx.x; k < HH; k += 128)
        s += g_h2[(size_t)k * BB + b] * Wout[(size_t)k * LL + n];
    __shared__ float red[4];
#pragma unroll
    for (int o = 16; o; o >>= 1) s += __shfl_down_sync(0xffffffffu, s, o);
    if ((threadIdx.x & 31) == 0) red[threadIdx.x >> 5] = s;
    __syncthreads();
    if (threadIdx.x == 0)
        out[b * LL + n] = red[0] + red[1] + red[2] + red[3] + bout[n];
}

// ---------------- launch ------------------------------------------------------
extern "C" void kernel_launch(void* const* d_in, const int* in_sizes, int n_in,
                              void* d_out, int out_size) {
    const float* x      = (const float*)d_in[0];
    const int*   eidx   = (const int*)d_in[1];
    const float* W_cls  = (const float*)d_in[2];
    const float* b_cls  = (const float*)d_in[3];
    const float* W_e1   = (const float*)d_in[4];
    const float* b_e1   = (const float*)d_in[5];
    const float* W_e2   = (const float*)d_in[6];
    const float* b_e2   = (const float*)d_in[7];
    const float* W1     = (const float*)d_in[8];
    const float* b1     = (const float*)d_in[9];
    const float* W2     = (const float*)d_in[10];
    const float* b2     = (const float*)d_in[11];
    const float* Wout   = (const float*)d_in[12];
    const float* bout   = (const float*)d_in[13];
    float* out = (float*)d_out;

    // 1) span means + tanh + bias concat (grid 64 x 4)
    prep_kernel<<<dim3(BB, HH / 256), 256>>>(x, eidx, b_cls, b_e1, b_e2);

    // 2) GEMM1: [64,1024] x block-diag(W_cls,W_e1,W_e2) -> [3072][64]
    //    grid 24 x 16 = 384 CTAs, kchunk 64
    gemm_split<<<dim3(3 * HH / BNN, 16), 128>>>(0, W_cls, W_e1, W_e2,
                                                HH, 3 * HH, HH, 64);
    reduce_bias<<<(3 * HH * BB / 4 + 511) / 512, 512>>>(nullptr, 0, 3 * HH, 16);

    // 3) GEMM2: [64,3072] @ W1[3072,1024], grid 8 x 48 = 384 CTAs, kchunk 64
    gemm_split<<<dim3(HH / BNN, 48), 128>>>(1, W1, nullptr, nullptr,
                                            0, HH, HH, 64);
    reduce_bias<<<(HH * BB / 4 + 511) / 512, 512>>>(b1, 1, HH, 48);

    // 4) GEMM3: [64,1024] @ W2[1024,1024], grid 8 x 32 = 256 CTAs, kchunk 32
    gemm_split<<<dim3(HH / BNN, 32), 128>>>(2, W2, nullptr, nullptr,
                                            0, HH, HH, 32);
    reduce_bias<<<(HH * BB / 4 + 511) / 512, 512>>>(b2, 2, HH, 32);

    // 5) output projection
    out_gemm<<<dim3(LL, BB), 128>>>(Wout, bout, out);

    (void)in_sizes; (void)n_in; (void)out_size;
}

// round 9
// speedup vs baseline: 1.4162x; 1.4162x over previous
#include <cuda_runtime.h>
#include <cstdint>

#define BB 64
#define HH 1024
#define SS 2048
#define LL 15
#define BKK 16
#define BNN 128

typedef unsigned long long ull;

// ---------------- scratch (static device globals; no allocation) ------------
// Activations K-major plain float: A[k*64 + b]
__device__ float g_T[3 * HH * BB];      // tanh prep outputs
__device__ float g_bcat[3 * HH];        // concat(b_cls,b_e1,b_e2)
__device__ float g_H3[3 * HH * BB];     // GEMM1 output [3H][B]
__device__ float g_h1[HH * BB];         // GEMM2 output [H][B]
__device__ float g_h2[HH * BB];         // GEMM3 output [H][B]
__device__ float g_P[48 * HH * BB];     // split-K partials [q][n][b]

// ---------------- f32x2 packed helpers --------------------------------------
__device__ __forceinline__ ull pack2(float x) {
    ull r; unsigned xi = __float_as_uint(x);
    asm("mov.b64 %0, {%1, %1};" : "=l"(r) : "r"(xi));
    return r;
}
__device__ __forceinline__ void ffma2(ull& acc, ull a, ull b) {
    asm("fma.rn.f32x2 %0, %1, %2, %3;" : "=l"(acc) : "l"(a), "l"(b), "l"(acc));
}
__device__ __forceinline__ float2 unpack2(ull v) {
    unsigned lo, hi;
    asm("mov.b64 {%0, %1}, %2;" : "=r"(lo), "=r"(hi) : "l"(v));
    float2 f; f.x = __uint_as_float(lo); f.y = __uint_as_float(hi);
    return f;
}

// ---------------- cp.async helpers ------------------------------------------
__device__ __forceinline__ void cp16(void* s, const void* g) {
    unsigned ss = (unsigned)__cvta_generic_to_shared(s);
    asm volatile("cp.async.cg.shared.global [%0], [%1], 16;" :: "r"(ss), "l"(g));
}
#define CP_COMMIT asm volatile("cp.async.commit_group;")
__device__ __forceinline__ void cp_wait_n(int n) {
    // n is compile-time constant after full unroll; switch folds away.
    switch (n) {
        case 0: asm volatile("cp.async.wait_group 0;"); break;
        case 1: asm volatile("cp.async.wait_group 1;"); break;
        case 2: asm volatile("cp.async.wait_group 2;"); break;
        default: asm volatile("cp.async.wait_group 3;"); break;
    }
}

// ---------------- prep: span means + tanh + bias concat ---------------------
__global__ void prep_kernel(const float* __restrict__ x,
                            const int* __restrict__ eidx,
                            const float* __restrict__ b_cls,
                            const float* __restrict__ b_e1,
                            const float* __restrict__ b_e2) {
    int b = blockIdx.x;
    int tid = threadIdx.x;  // 256
    int h = blockIdx.y * 256 + tid;

    if (blockIdx.y == 0 && b < 12) {
        int gidx = b * 256 + tid;
        if (gidx < HH)          g_bcat[gidx] = b_cls[gidx];
        else if (gidx < 2 * HH) g_bcat[gidx] = b_e1[gidx - HH];
        else                    g_bcat[gidx] = b_e2[gidx - 2 * HH];
    }

    int s1 = eidx[b * 4 + 0], e1 = eidx[b * 4 + 1];
    int s2 = eidx[b * 4 + 2], e2 = eidx[b * 4 + 3];
    float c1 = 1.0f / (float)max(e1 - s1, 1);
    float c2 = 1.0f / (float)max(e2 - s2, 1);
    const float* xb = x + (size_t)b * SS * HH;

    float t0 = tanhf(xb[h]);
    float a1 = 0.f;
    for (int p = s1; p < e1; ++p) a1 += xb[(size_t)p * HH + h];
    float a2 = 0.f;
    for (int p = s2; p < e2; ++p) a2 += xb[(size_t)p * HH + h];
    g_T[(size_t)(0 * HH + h) * BB + b] = t0;
    g_T[(size_t)(1 * HH + h) * BB + b] = tanhf(a1 * c1);
    g_T[(size_t)(2 * HH + h) * BB + b] = tanhf(a2 * c2);
}

// ---------------- split-K skinny GEMM: FULL-kchunk prefetch ------------------
// All NT tiles cp.async'd in the prologue (one commit group per tile), then
// drained with decreasing wait_group. DRAM latency paid once per CTA.
// X K-major [K][64] plain float in smem (warp-broadcast LDS). W conflict-free.
// Block tile 64(b) x 128(n), BK=16, 128 threads, thread tile 8b x 8n.
template<int NT>
__global__ __launch_bounds__(128)
void gemm_split(int xsel,                    // 0: g_T, 1: g_H3, 2: g_h1
                const float* __restrict__ W0,
                const float* __restrict__ We1,
                const float* __restrict__ We2,
                int seg,                     // 0: single weight; else cols/segment
                int Ntot, int ldw) {
    const float* X = (xsel == 0) ? g_T : (xsel == 1) ? g_H3 : g_h1;
    int n0 = blockIdx.x * BNN;
    const float* W = W0;
    int ncol = n0;
    if (seg) {
        int which = n0 / seg;
        W = (which == 0) ? W0 : (which == 1 ? We1 : We2);
        ncol = n0 - which * seg;
        X += (size_t)which * HH * BB;   // segment rows
    }
    int kbeg = blockIdx.y * (NT * BKK);

    __shared__ float Xs[NT][BKK][BB];    // NT x 4KB
    __shared__ float Ws[NT][BKK][BNN];   // NT x 8KB

    int tid = threadIdx.x;
    int tn = tid & 15;   // n group 0..15
    int tb = tid >> 4;   // b group 0..7 (8 rows each)

    ull acc[8][4];
#pragma unroll
    for (int i = 0; i < 8; i++)
#pragma unroll
        for (int j = 0; j < 4; j++) acc[i][j] = 0ULL;

    // --- prologue: stage ALL tiles, one commit group each ---
#pragma unroll
    for (int tt = 0; tt < NT; tt++) {
        int k0 = kbeg + tt * BKK;
#pragma unroll
        for (int i = 0; i < 2; i++) {
            int p = tid + 128 * i;                 // 0..255
            int r = p >> 4, c = (p & 15) * 4;      // 16 rows x 16 chunks of 4 floats
            cp16(&Xs[tt][r][c], X + (size_t)(k0 + r) * BB + c);
        }
#pragma unroll
        for (int i = 0; i < 4; i++) {
            int p = tid + 128 * i;                 // 0..511
            int r = p >> 5, c = (p & 31) * 4;      // 16 rows x 32 chunks of 4 floats
            cp16(&Ws[tt][r][c], W + (size_t)(k0 + r) * ldw + ncol + c);
        }
        CP_COMMIT;
    }

    // --- drain: compute tile t once its group has landed ---
#pragma unroll
    for (int t = 0; t < NT; t++) {
        cp_wait_n(NT - 1 - t);    // groups t+1..NT-1 may still be in flight
        __syncthreads();          // make tile t's smem visible to all warps

#pragma unroll
        for (int kk = 0; kk < BKK; ++kk) {
            float4 xa = *(const float4*)&Xs[t][kk][tb * 8];      // broadcast LDS
            float4 xc = *(const float4*)&Xs[t][kk][tb * 8 + 4];
            ull x2[8];
            x2[0] = pack2(xa.x); x2[1] = pack2(xa.y);
            x2[2] = pack2(xa.z); x2[3] = pack2(xa.w);
            x2[4] = pack2(xc.x); x2[5] = pack2(xc.y);
            x2[6] = pack2(xc.z); x2[7] = pack2(xc.w);
            // conflict-free W: lane-stride 16B within each 128B phase
            ulonglong2 wv0 = *(const ulonglong2*)&Ws[t][kk][tn * 4];       // n=tn*4..+3
            ulonglong2 wv1 = *(const ulonglong2*)&Ws[t][kk][64 + tn * 4];  // n=64+tn*4..+3
            ull w2[4]; w2[0] = wv0.x; w2[1] = wv0.y; w2[2] = wv1.x; w2[3] = wv1.y;
#pragma unroll
            for (int i = 0; i < 8; i++)
#pragma unroll
                for (int j = 0; j < 4; j++) ffma2(acc[i][j], x2[i], w2[j]);
        }
    }

    // --- write partials: P[(q*Ntot + n)*64 + b]
    float* pbase = g_P + ((size_t)blockIdx.y * Ntot + n0) * BB + tb * 8;
#pragma unroll
    for (int j = 0; j < 4; j++) {
        int nrow = (j < 2) ? (tn * 4 + 2 * j) : (64 + tn * 4 + 2 * (j - 2));
        float2 f0 = unpack2(acc[0][j]), f1 = unpack2(acc[1][j]);
        float2 f2 = unpack2(acc[2][j]), f3 = unpack2(acc[3][j]);
        float2 f4 = unpack2(acc[4][j]), f5 = unpack2(acc[5][j]);
        float2 f6 = unpack2(acc[6][j]), f7 = unpack2(acc[7][j]);
        float* r0 = pbase + (size_t)nrow * BB;
        *(float4*)r0       = make_float4(f0.x, f1.x, f2.x, f3.x);
        *(float4*)(r0 + 4) = make_float4(f4.x, f5.x, f6.x, f7.x);
        float* r1 = pbase + (size_t)(nrow + 1) * BB;
        *(float4*)r1       = make_float4(f0.y, f1.y, f2.y, f3.y);
        *(float4*)(r1 + 4) = make_float4(f4.y, f5.y, f6.y, f7.y);
    }
}

// ---------------- reduce split-K partials + bias (layout [n][b]) -------------
__global__ __launch_bounds__(512)
void reduce_bias(const float* __restrict__ bias,  // nullptr -> g_bcat
                 int ysel,                        // 0:g_H3 1:g_h1 2:g_h2
                 int Ntot, int ks) {
    float* Y = (ysel == 0) ? g_H3 : (ysel == 1) ? g_h1 : g_h2;
    const float* bp = bias ? bias : g_bcat;
    int idx = blockIdx.x * 512 + threadIdx.x;     // float4 index over Ntot*BB
    int total = Ntot * BB / 4;
    if (idx >= total) return;
    const float4* P4 = (const float4*)g_P;
    float4 s = __ldg(&P4[idx]);
#pragma unroll 4
    for (int q = 1; q < ks; q++) {
        float4 v = __ldg(&P4[(size_t)q * total + idx]);
        s.x += v.x; s.y += v.y; s.z += v.z; s.w += v.w;
    }
    int n = idx >> 4;            // 16 float4 per n row (BB=64)
    float bv = bp[n];
    s.x += bv; s.y += bv; s.z += bv; s.w += bv;
    ((float4*)Y)[idx] = s;
}

// ---------------- tiny output GEMM: h2[n][b] x Wout[1024,15] -----------------
__global__ void out_gemm(const float* __restrict__ Wout,
                         const float* __restrict__ bout,
                         float* __restrict__ out) {
    int n = blockIdx.x;   // 0..14
    int b = blockIdx.y;   // 0..63
    float s = 0.f;
    for (int k = threadIdx.x; k < HH; k += 128)
        s += g_h2[(size_t)k * BB + b] * Wout[(size_t)k * LL + n];
    __shared__ float red[4];
#pragma unroll
    for (int o = 16; o; o >>= 1) s += __shfl_down_sync(0xffffffffu, s, o);
    if ((threadIdx.x & 31) == 0) red[threadIdx.x >> 5] = s;
    __syncthreads();
    if (threadIdx.x == 0)
        out[b * LL + n] = red[0] + red[1] + red[2] + red[3] + bout[n];
}

// ---------------- launch ------------------------------------------------------
extern "C" void kernel_launch(void* const* d_in, const int* in_sizes, int n_in,
                              void* d_out, int out_size) {
    const float* x      = (const float*)d_in[0];
    const int*   eidx   = (const int*)d_in[1];
    const float* W_cls  = (const float*)d_in[2];
    const float* b_cls  = (const float*)d_in[3];
    const float* W_e1   = (const float*)d_in[4];
    const float* b_e1   = (const float*)d_in[5];
    const float* W_e2   = (const float*)d_in[6];
    const float* b_e2   = (const float*)d_in[7];
    const float* W1     = (const float*)d_in[8];
    const float* b1     = (const float*)d_in[9];
    const float* W2     = (const float*)d_in[10];
    const float* b2     = (const float*)d_in[11];
    const float* Wout   = (const float*)d_in[12];
    const float* bout   = (const float*)d_in[13];
    float* out = (float*)d_out;

    // 1) span means + tanh + bias concat (grid 64 x 4)
    prep_kernel<<<dim3(BB, HH / 256), 256>>>(x, eidx, b_cls, b_e1, b_e2);

    // 2) GEMM1: [64,1024] x block-diag(W_cls,W_e1,W_e2) -> [3072][64]
    //    grid 24 x 16 = 384 CTAs, kchunk 64 = 4 fully-prefetched tiles
    gemm_split<4><<<dim3(3 * HH / BNN, 16), 128>>>(0, W_cls, W_e1, W_e2,
                                                   HH, 3 * HH, HH);
    reduce_bias<<<(3 * HH * BB / 4 + 511) / 512, 512>>>(nullptr, 0, 3 * HH, 16);

    // 3) GEMM2: [64,3072] @ W1[3072,1024], grid 8 x 48 = 384 CTAs, kchunk 64
    gemm_split<4><<<dim3(HH / BNN, 48), 128>>>(1, W1, nullptr, nullptr,
                                               0, HH, HH);
    reduce_bias<<<(HH * BB / 4 + 511) / 512, 512>>>(b1, 1, HH, 48);

    // 4) GEMM3: [64,1024] @ W2[1024,1024], grid 8 x 32 = 256 CTAs, kchunk 32
    gemm_split<2><<<dim3(HH / BNN, 32), 128>>>(2, W2, nullptr, nullptr,
                                               0, HH, HH);
    reduce_bias<<<(HH * BB / 4 + 511) / 512, 512>>>(b2, 2, HH, 32);

    // 5) output projection
    out_gemm<<<dim3(LL, BB), 128>>>(Wout, bout, out);

    (void)in_sizes; (void)n_in; (void)out_size;
}

// round 11
// speedup vs baseline: 1.4570x; 1.0288x over previous
#include <cuda_runtime.h>
#include <cuda_bf16.h>
#include <cstdint>

#define BB 64
#define HH 1024
#define SS 2048
#define LL 15

using bf16 = __nv_bfloat16;
typedef unsigned long long ull;

// ---------------- scratch (static device globals; no allocation) ------------
__device__ __align__(16) bf16 g_W1th[3*HH*HH], g_W1tl[3*HH*HH]; // [3072 n][1024 k]
__device__ __align__(16) bf16 g_W2th[HH*3*HH], g_W2tl[HH*3*HH]; // [1024 n][3072 k]
__device__ __align__(16) bf16 g_W3th[HH*HH],   g_W3tl[HH*HH];   // [1024][1024]
__device__ __align__(16) bf16 g_X1h[3*BB*HH],  g_X1l[3*BB*HH];  // [3 seg][64 b][1024 k]
__device__ __align__(16) bf16 g_X2h[BB*3*HH],  g_X2l[BB*3*HH];  // [64 b][3072 k]
__device__ __align__(16) bf16 g_X3h[BB*HH],    g_X3l[BB*HH];    // [64 b][1024 k]
__device__ __align__(16) float g_h2[BB*HH];                     // [64 b][1024 k]
__device__ __align__(16) float g_bcat[3*HH];
__device__ __align__(16) float g_P[48*HH*BB];                   // split-K partials [q][n][b]

// ---------------- PTX helpers ------------------------------------------------
__device__ __forceinline__ uint32_t smem_u32(const void* p) {
    uint32_t a;
    asm("{ .reg .u64 t; cvta.to.shared.u64 t, %1; cvt.u32.u64 %0, t; }" : "=r"(a) : "l"(p));
    return a;
}
__device__ __forceinline__ void cp16s(uint32_t saddr, const void* g) {
    asm volatile("cp.async.cg.shared.global [%0], [%1], 16;" :: "r"(saddr), "l"(g));
}
#define CP_COMMIT asm volatile("cp.async.commit_group;")
__device__ __forceinline__ void cp_wait_n(int n) {
    switch (n) {
        case 0: asm volatile("cp.async.wait_group 0;"); break;
        case 1: asm volatile("cp.async.wait_group 1;"); break;
        case 2: asm volatile("cp.async.wait_group 2;"); break;
        default: asm volatile("cp.async.wait_group 3;"); break;
    }
}
__device__ __forceinline__ void ldmat4(uint32_t (&r)[4], uint32_t addr) {
    asm volatile("ldmatrix.sync.aligned.m8n8.x4.shared.b16 {%0,%1,%2,%3}, [%4];"
                 : "=r"(r[0]), "=r"(r[1]), "=r"(r[2]), "=r"(r[3]) : "r"(addr));
}
__device__ __forceinline__ void mma16816(float (&d)[4], const uint32_t (&a)[4],
                                         uint32_t b0, uint32_t b1) {
    asm volatile("mma.sync.aligned.m16n8k16.row.col.f32.bf16.bf16.f32 "
                 "{%0,%1,%2,%3}, {%4,%5,%6,%7}, {%8,%9}, {%0,%1,%2,%3};"
                 : "+f"(d[0]), "+f"(d[1]), "+f"(d[2]), "+f"(d[3])
                 : "r"(a[0]), "r"(a[1]), "r"(a[2]), "r"(a[3]), "r"(b0), "r"(b1));
}

// ---------------- prep: span means + tanh + bf16 split ----------------------
__global__ void prep_kernel(const float* __restrict__ x,
                            const int* __restrict__ eidx,
                            const float* __restrict__ b_cls,
                            const float* __restrict__ b_e1,
                            const float* __restrict__ b_e2) {
    int b = blockIdx.x;
    int tid = threadIdx.x;  // 256
    int h = blockIdx.y * 256 + tid;

    if (blockIdx.y == 0 && b < 12) {
        int gidx = b * 256 + tid;
        if (gidx < HH)          g_bcat[gidx] = b_cls[gidx];
        else if (gidx < 2 * HH) g_bcat[gidx] = b_e1[gidx - HH];
        else                    g_bcat[gidx] = b_e2[gidx - 2 * HH];
    }

    int s1 = eidx[b * 4 + 0], e1 = eidx[b * 4 + 1];
    int s2 = eidx[b * 4 + 2], e2 = eidx[b * 4 + 3];
    float c1 = 1.0f / (float)max(e1 - s1, 1);
    float c2 = 1.0f / (float)max(e2 - s2, 1);
    const float* xb = x + (size_t)b * SS * HH;

    float a1 = 0.f;
    for (int p = s1; p < e1; ++p) a1 += xb[(size_t)p * HH + h];
    float a2 = 0.f;
    for (int p = s2; p < e2; ++p) a2 += xb[(size_t)p * HH + h];
    float v[3] = { tanhf(xb[h]), tanhf(a1 * c1), tanhf(a2 * c2) };
#pragma unroll
    for (int s = 0; s < 3; s++) {
        size_t idx = ((size_t)(s * BB + b)) * HH + h;
        bf16 hv = __float2bfloat16(v[s]);
        bf16 lv = __float2bfloat16(v[s] - __bfloat162float(hv));
        g_X1h[idx] = hv;
        g_X1l[idx] = lv;
    }
}

// ---------------- weight transpose + bf16 hi/lo split ------------------------
// In: W [K][N] fp32 row-major. Out: Wt_hi/lo [N][K] bf16.
__global__ void convW(const float* __restrict__ W, int K, int N,
                      int dst, size_t off) {
    __shared__ float S[32][33];
    int n0 = blockIdx.x * 32, k0 = blockIdx.y * 32;
    int tx = threadIdx.x, ty = threadIdx.y;  // 32 x 8
#pragma unroll
    for (int i = 0; i < 4; i++)
        S[ty + 8 * i][tx] = W[(size_t)(k0 + ty + 8 * i) * N + n0 + tx];
    __syncthreads();
    bf16 *Th, *Tl;
    if (dst == 0)      { Th = g_W1th; Tl = g_W1tl; }
    else if (dst == 1) { Th = g_W2th; Tl = g_W2tl; }
    else               { Th = g_W3th; Tl = g_W3tl; }
    Th += off; Tl += off;
#pragma unroll
    for (int i = 0; i < 4; i++) {
        int r = ty + 8 * i;
        float v = S[tx][r];                 // (k=k0+tx, n=n0+r)
        bf16 h = __float2bfloat16(v);
        bf16 l = __float2bfloat16(v - __bfloat162float(h));
        Th[(size_t)(n0 + r) * K + k0 + tx] = h;
        Tl[(size_t)(n0 + r) * K + k0 + tx] = l;
    }
}

// ---------------- HMMA split-K GEMM (mma.sync m16n8k16 bf16, 2-split) --------
// D[n 128][b 64] per CTA. 4 warps, warp w owns n rows [w*32, w*32+32).
// Tiles in smem at 80B row pitch (conflict-free ldmatrix, no XOR swizzle).
// NT slabs of BK=32 fully prefetched (one commit group per slab).
template<int NT>
__global__ __launch_bounds__(128)
void gemm_mma(int wsel, int nseg, int Kt, int Ntot) {
    extern __shared__ char smem[];
    constexpr int WSLAB = 128 * 80;   // 10240 B
    constexpr int XSLAB = 64 * 80;    // 5120 B
    const int WHo = 0;
    const int WLo = NT * WSLAB;
    const int XHo = 2 * NT * WSLAB;
    const int XLo = XHo + NT * XSLAB;
    uint32_t sb = smem_u32(smem);

    int tid = threadIdx.x, w = tid >> 5, lane = tid & 31;
    int n0 = blockIdx.x * 128;
    int kbeg = blockIdx.y * (NT * 32);

    const bf16 *Whp, *Wlp, *Xhp, *Xlp;
    if (wsel == 0)      { Whp = g_W1th; Wlp = g_W1tl; Xhp = g_X1h; Xlp = g_X1l; }
    else if (wsel == 1) { Whp = g_W2th; Wlp = g_W2tl; Xhp = g_X2h; Xlp = g_X2l; }
    else                { Whp = g_W3th; Wlp = g_W3tl; Xhp = g_X3h; Xlp = g_X3l; }
    if (nseg) {
        size_t xoff = (size_t)(n0 / nseg) * BB * Kt;
        Xhp += xoff; Xlp += xoff;
    }

    // --- prologue: stage all NT slabs, one commit group each ---
#pragma unroll
    for (int tt = 0; tt < NT; tt++) {
        int k0 = kbeg + tt * 32;
#pragma unroll
        for (int i = 0; i < 4; i++) {          // W: 128 rows x 4 chunks
            int q = tid + 128 * i;
            int r = q >> 2, c = q & 3;
            uint32_t doff = (uint32_t)(r * 80 + c * 16);
            const size_t so = (size_t)(n0 + r) * Kt + k0 + c * 8;
            cp16s(sb + WHo + tt * WSLAB + doff, Whp + so);
            cp16s(sb + WLo + tt * WSLAB + doff, Wlp + so);
        }
#pragma unroll
        for (int i = 0; i < 2; i++) {          // X: 64 rows x 4 chunks
            int q = tid + 128 * i;
            int r = q >> 2, c = q & 3;
            uint32_t doff = (uint32_t)(r * 80 + c * 16);
            const size_t so = (size_t)r * Kt + k0 + c * 8;
            cp16s(sb + XHo + tt * XSLAB + doff, Xhp + so);
            cp16s(sb + XLo + tt * XSLAB + doff, Xlp + so);
        }
        CP_COMMIT;
    }

    float d[2][8][4] = {};

    // per-lane ldmatrix source offsets (ldmatrix m8n8 lane-group convention)
    int rowA = (lane & 7) + ((lane >> 3) & 1) * 8;   // groups: r0-7 c0, r8-15 c0, r0-7 c1, r8-15 c1
    int cA = lane >> 4;
    uint32_t pA = (uint32_t)((w * 32 + rowA) * 80 + cA * 16);
    int rowX = (lane & 7) + (lane >> 4) * 8;         // groups: r0-7 c0, r0-7 c1, r8-15 c0, r8-15 c1
    int cX = (lane >> 3) & 1;
    uint32_t pB = (uint32_t)(rowX * 80 + cX * 16);

#pragma unroll
    for (int tt = 0; tt < NT; tt++) {
        cp_wait_n(NT - 1 - tt);
        __syncthreads();

#pragma unroll
        for (int s = 0; s < 2; s++) {          // two k16 steps per BK=32 slab
            uint32_t ko = s * 32;              // byte offset within 64B of data
            uint32_t ah[2][4], al[2][4];
            ldmat4(ah[0], sb + WHo + tt * WSLAB + pA + ko);
            ldmat4(ah[1], sb + WHo + tt * WSLAB + pA + ko + 16 * 80);
            ldmat4(al[0], sb + WLo + tt * WSLAB + pA + ko);
            ldmat4(al[1], sb + WLo + tt * WSLAB + pA + ko + 16 * 80);
            uint32_t bh[4][4], bl[4][4];
#pragma unroll
            for (int p = 0; p < 4; p++) {      // 4 x (16 b-rows)
                ldmat4(bh[p], sb + XHo + tt * XSLAB + pB + ko + p * 16 * 80);
                ldmat4(bl[p], sb + XLo + tt * XSLAB + pB + ko + p * 16 * 80);
            }
#pragma unroll
            for (int mt = 0; mt < 2; mt++)
#pragma unroll
                for (int nt = 0; nt < 8; nt++) {
                    int p = nt >> 1, hf = (nt & 1) * 2;
                    mma16816(d[mt][nt], ah[mt], bh[p][hf], bh[p][hf + 1]);
                    mma16816(d[mt][nt], ah[mt], bl[p][hf], bl[p][hf + 1]);
                    mma16816(d[mt][nt], al[mt], bh[p][hf], bh[p][hf + 1]);
                }
        }
    }

    // --- epilogue: P[(q*Ntot + n)*64 + b] ---
    float* pq = g_P + (size_t)blockIdx.y * Ntot * BB;
#pragma unroll
    for (int mt = 0; mt < 2; mt++)
#pragma unroll
        for (int nt = 0; nt < 8; nt++) {
            int n = n0 + w * 32 + mt * 16 + (lane >> 2);
            int b = nt * 8 + (lane & 3) * 2;
            *(float2*)&pq[(size_t)n * BB + b]       = make_float2(d[mt][nt][0], d[mt][nt][1]);
            *(float2*)&pq[(size_t)(n + 8) * BB + b] = make_float2(d[mt][nt][2], d[mt][nt][3]);
        }
}

// ---------------- transposing reduce: P[q][n][b] -> b-major output -----------
// ysel 0: -> g_X2 (bf16 hi/lo, bias=g_bcat), 1: -> g_X3 (bias), 2: -> g_h2 fp32
__global__ __launch_bounds__(256)
void reduceT(const float* __restrict__ bias, int ysel, int Ntot, int ks) {
    __shared__ float S[16][66];
    int n0 = blockIdx.x * 16;
    int t = threadIdx.x;
    int nl = t >> 4, b4 = t & 15;
    int n = n0 + nl;
    const float* p = g_P + (size_t)n * BB + b4 * 4;
    float4 s = *(const float4*)p;
    for (int q = 1; q < ks; q++) {
        float4 v = *(const float4*)(p + (size_t)q * Ntot * BB);
        s.x += v.x; s.y += v.y; s.z += v.z; s.w += v.w;
    }
    float bv = (ysel == 0) ? g_bcat[n] : bias[n];
    s.x += bv; s.y += bv; s.z += bv; s.w += bv;
    S[nl][b4 * 4 + 0] = s.x; S[nl][b4 * 4 + 1] = s.y;
    S[nl][b4 * 4 + 2] = s.z; S[nl][b4 * 4 + 3] = s.w;
    __syncthreads();

    int b = t >> 2, nn = (t & 3) * 4;
    float v0 = S[nn + 0][b], v1 = S[nn + 1][b], v2 = S[nn + 2][b], v3 = S[nn + 3][b];
    if (ysel == 2) {
        *(float4*)&g_h2[(size_t)b * Ntot + n0 + nn] = make_float4(v0, v1, v2, v3);
    } else {
        bf16* Yh = (ysel == 0) ? g_X2h : g_X3h;
        bf16* Yl = (ysel == 0) ? g_X2l : g_X3l;
        bf16 h0 = __float2bfloat16(v0), h1 = __float2bfloat16(v1);
        bf16 h2 = __float2bfloat16(v2), h3 = __float2bfloat16(v3);
        bf16 l0 = __float2bfloat16(v0 - __bfloat162float(h0));
        bf16 l1 = __float2bfloat16(v1 - __bfloat162float(h1));
        bf16 l2 = __float2bfloat16(v2 - __bfloat162float(h2));
        bf16 l3 = __float2bfloat16(v3 - __bfloat162float(h3));
        size_t o = (size_t)b * Ntot + n0 + nn;
        *(__nv_bfloat162*)&Yh[o]     = __nv_bfloat162(h0, h1);
        *(__nv_bfloat162*)&Yh[o + 2] = __nv_bfloat162(h2, h3);
        *(__nv_bfloat162*)&Yl[o]     = __nv_bfloat162(l0, l1);
        *(__nv_bfloat162*)&Yl[o + 2] = __nv_bfloat162(l2, l3);
    }
}

// ---------------- tiny output GEMM: h2[b][k] x Wout[1024,15] -----------------
__global__ void out_gemm(const float* __restrict__ Wout,
                         const float* __restrict__ bout,
                         float* __restrict__ out) {
    int n = blockIdx.x;   // 0..14
    int b = blockIdx.y;   // 0..63
    float s = 0.f;
    for (int k = threadIdx.x; k < HH; k += 128)
        s += g_h2[(size_t)b * HH + k] * Wout[(size_t)k * LL + n];
    __shared__ float red[4];
#pragma unroll
    for (int o = 16; o; o >>= 1) s += __shfl_down_sync(0xffffffffu, s, o);
    if ((threadIdx.x & 31) == 0) red[threadIdx.x >> 5] = s;
    __syncthreads();
    if (threadIdx.x == 0)
        out[b * LL + n] = red[0] + red[1] + red[2] + red[3] + bout[n];
}

// ---------------- launch ------------------------------------------------------
extern "C" void kernel_launch(void* const* d_in, const int* in_sizes, int n_in,
                              void* d_out, int out_size) {
    const float* x      = (const float*)d_in[0];
    const int*   eidx   = (const int*)d_in[1];
    const float* W_cls  = (const float*)d_in[2];
    const float* b_cls  = (const float*)d_in[3];
    const float* W_e1   = (const float*)d_in[4];
    const float* b_e1   = (const float*)d_in[5];
    const float* W_e2   = (const float*)d_in[6];
    const float* b_e2   = (const float*)d_in[7];
    const float* W1     = (const float*)d_in[8];
    const float* b1     = (const float*)d_in[9];
    const float* W2     = (const float*)d_in[10];
    const float* b2     = (const float*)d_in[11];
    const float* Wout   = (const float*)d_in[12];
    const float* bout   = (const float*)d_in[13];
    float* out = (float*)d_out;

    const int GSMEM = 2 * (2 * 128 * 80 + 2 * 64 * 80);  // NT=2: 61440 B
    cudaFuncSetAttribute(gemm_mma<2>, cudaFuncAttributeMaxDynamicSharedMemorySize,
                         GSMEM);

    // 1) prep + weight conversions
    prep_kernel<<<dim3(BB, HH / 256), 256>>>(x, eidx, b_cls, b_e1, b_e2);
    convW<<<dim3(32, 32), dim3(32, 8)>>>(W_cls, HH, HH, 0, 0);
    convW<<<dim3(32, 32), dim3(32, 8)>>>(W_e1,  HH, HH, 0, (size_t)HH * HH);
    convW<<<dim3(32, 32), dim3(32, 8)>>>(W_e2,  HH, HH, 0, (size_t)2 * HH * HH);
    convW<<<dim3(32, 96), dim3(32, 8)>>>(W1, 3 * HH, HH, 1, 0);
    convW<<<dim3(32, 32), dim3(32, 8)>>>(W2, HH, HH, 2, 0);

    // 2) GEMM1: block-diag(W_cls,W_e1,W_e2)^T x tanh-feats (24 x 16 CTAs, kchunk 64)
    gemm_mma<2><<<dim3(24, 16), 128, GSMEM>>>(0, HH, HH, 3 * HH);
    reduceT<<<3 * HH / 16, 256>>>(nullptr, 0, 3 * HH, 16);

    // 3) GEMM2: W1^T x H3 (8 x 48 CTAs, K=3072)
    gemm_mma<2><<<dim3(8, 48), 128, GSMEM>>>(1, 0, 3 * HH, HH);
    reduceT<<<HH / 16, 256>>>(b1, 1, HH, 48);

    // 4) GEMM3: W2^T x h1 (8 x 16 CTAs)
    gemm_mma<2><<<dim3(8, 16), 128, GSMEM>>>(2, 0, HH, HH);
    reduceT<<<HH / 16, 256>>>(b2, 2, HH, 16);

    // 5) output projection
    out_gemm<<<dim3(LL, BB), 128>>>(Wout, bout, out);

    (void)in_sizes; (void)n_in; (void)out_size;
}

// round 12
// speedup vs baseline: 1.6851x; 1.1565x over previous
#include <cuda_runtime.h>
#include <cuda_bf16.h>
#include <cstdint>

#define BB 64
#define HH 1024
#define SS 2048
#define LL 15

using bf16 = __nv_bfloat16;
typedef unsigned long long ull;

// ---------------- scratch (static device globals; no allocation) ------------
__device__ __align__(16) bf16 g_W1th[3*HH*HH], g_W1tl[3*HH*HH]; // [3072 n][1024 k]
__device__ __align__(16) bf16 g_W2th[HH*3*HH], g_W2tl[HH*3*HH]; // [1024 n][3072 k]
__device__ __align__(16) bf16 g_W3th[HH*HH],   g_W3tl[HH*HH];   // [1024][1024]
__device__ __align__(16) bf16 g_X1h[3*BB*HH],  g_X1l[3*BB*HH];  // [3 seg][64 b][1024 k]
__device__ __align__(16) bf16 g_X2h[BB*3*HH],  g_X2l[BB*3*HH];  // [64 b][3072 k]
__device__ __align__(16) bf16 g_X3h[BB*HH],    g_X3l[BB*HH];    // [64 b][1024 k]
__device__ __align__(16) float g_h2[BB*HH];                     // [64 b][1024 k]
__device__ __align__(16) float g_bcat[3*HH];
__device__ __align__(16) float g_P[48*HH*BB];                   // split-K partials [q][n][b]

// ---------------- PTX helpers ------------------------------------------------
__device__ __forceinline__ uint32_t smem_u32(const void* p) {
    uint32_t a;
    asm("{ .reg .u64 t; cvta.to.shared.u64 t, %1; cvt.u32.u64 %0, t; }" : "=r"(a) : "l"(p));
    return a;
}
__device__ __forceinline__ void cp16s(uint32_t saddr, const void* g) {
    asm volatile("cp.async.cg.shared.global [%0], [%1], 16;" :: "r"(saddr), "l"(g));
}
#define CP_COMMIT asm volatile("cp.async.commit_group;")
__device__ __forceinline__ void cp_wait_n(int n) {
    switch (n) {
        case 0: asm volatile("cp.async.wait_group 0;"); break;
        case 1: asm volatile("cp.async.wait_group 1;"); break;
        case 2: asm volatile("cp.async.wait_group 2;"); break;
        default: asm volatile("cp.async.wait_group 3;"); break;
    }
}
__device__ __forceinline__ void ldmat4(uint32_t (&r)[4], uint32_t addr) {
    asm volatile("ldmatrix.sync.aligned.m8n8.x4.shared.b16 {%0,%1,%2,%3}, [%4];"
                 : "=r"(r[0]), "=r"(r[1]), "=r"(r[2]), "=r"(r[3]) : "r"(addr));
}
__device__ __forceinline__ void mma16816(float (&d)[4], const uint32_t (&a)[4],
                                         uint32_t b0, uint32_t b1) {
    asm volatile("mma.sync.aligned.m16n8k16.row.col.f32.bf16.bf16.f32 "
                 "{%0,%1,%2,%3}, {%4,%5,%6,%7}, {%8,%9}, {%0,%1,%2,%3};"
                 : "+f"(d[0]), "+f"(d[1]), "+f"(d[2]), "+f"(d[3])
                 : "r"(a[0]), "r"(a[1]), "r"(a[2]), "r"(a[3]), "r"(b0), "r"(b1));
}

// ---------------- prep: span means + tanh + bf16 split ----------------------
__global__ void prep_kernel(const float* __restrict__ x,
                            const int* __restrict__ eidx,
                            const float* __restrict__ b_cls,
                            const float* __restrict__ b_e1,
                            const float* __restrict__ b_e2) {
    int b = blockIdx.x;
    int tid = threadIdx.x;  // 256
    int h = blockIdx.y * 256 + tid;

    if (blockIdx.y == 0 && b < 12) {
        int gidx = b * 256 + tid;
        if (gidx < HH)          g_bcat[gidx] = b_cls[gidx];
        else if (gidx < 2 * HH) g_bcat[gidx] = b_e1[gidx - HH];
        else                    g_bcat[gidx] = b_e2[gidx - 2 * HH];
    }

    int s1 = eidx[b * 4 + 0], e1 = eidx[b * 4 + 1];
    int s2 = eidx[b * 4 + 2], e2 = eidx[b * 4 + 3];
    float c1 = 1.0f / (float)max(e1 - s1, 1);
    float c2 = 1.0f / (float)max(e2 - s2, 1);
    const float* xb = x + (size_t)b * SS * HH;

    float a1 = 0.f;
    for (int p = s1; p < e1; ++p) a1 += xb[(size_t)p * HH + h];
    float a2 = 0.f;
    for (int p = s2; p < e2; ++p) a2 += xb[(size_t)p * HH + h];
    float v[3] = { tanhf(xb[h]), tanhf(a1 * c1), tanhf(a2 * c2) };
#pragma unroll
    for (int s = 0; s < 3; s++) {
        size_t idx = ((size_t)(s * BB + b)) * HH + h;
        bf16 hv = __float2bfloat16(v[s]);
        bf16 lv = __float2bfloat16(v[s] - __bfloat162float(hv));
        g_X1h[idx] = hv;
        g_X1l[idx] = lv;
    }
}

// ---------------- fused weight transpose + bf16 hi/lo split ------------------
// All 5 weights in ONE launch. 64x64 tile per block, 256 threads.
// Loads: float4 (128B/warp). Stores: uint4 = 8 bf16 (128B/warp-group).
__global__ __launch_bounds__(256)
void convAll(const float* __restrict__ Wc,  const float* __restrict__ We1,
             const float* __restrict__ We2, const float* __restrict__ W1,
             const float* __restrict__ W2) {
    __shared__ float S[64][65];
    int bid = blockIdx.x;
    const float* src; bf16 *Th, *Tl; int Ks; int base;
    if (bid < 256)       { src = Wc;  Th = g_W1th;                      Tl = g_W1tl;                      Ks = HH;     base = 0; }
    else if (bid < 512)  { src = We1; Th = g_W1th + (size_t)HH*HH;      Tl = g_W1tl + (size_t)HH*HH;      Ks = HH;     base = 256; }
    else if (bid < 768)  { src = We2; Th = g_W1th + (size_t)2*HH*HH;    Tl = g_W1tl + (size_t)2*HH*HH;    Ks = HH;     base = 512; }
    else if (bid < 1536) { src = W1;  Th = g_W2th;                      Tl = g_W2tl;                      Ks = 3*HH;   base = 768; }
    else                 { src = W2;  Th = g_W3th;                      Tl = g_W3tl;                      Ks = HH;     base = 1536; }
    int tw = bid - base;
    int kt = tw >> 4, nt = tw & 15;       // 16 n-tiles per K-row block (N=1024)
    int k0 = kt * 64, n0 = nt * 64;
    int t = threadIdx.x;

    // load 64x64 fp32 tile: row = k (src row), col = n; src cols = 1024
    int lr = t >> 4, lc = (t & 15) * 4;
#pragma unroll
    for (int i = 0; i < 4; i++) {
        float4 v = *(const float4*)(src + (size_t)(k0 + lr + 16 * i) * HH + n0 + lc);
        S[lr + 16 * i][lc + 0] = v.x; S[lr + 16 * i][lc + 1] = v.y;
        S[lr + 16 * i][lc + 2] = v.z; S[lr + 16 * i][lc + 3] = v.w;
    }
    __syncthreads();

    // store transposed: row = n, 8 consecutive k as uint4 (8 bf16)
    int k8 = (t & 7) * 8;
#pragma unroll
    for (int ii = 0; ii < 2; ii++) {
        int nl = (t >> 3) + 32 * ii;
        __nv_bfloat162 hh[4], ll[4];
#pragma unroll
        for (int j = 0; j < 4; j++) {
            float v0 = S[k8 + 2 * j][nl], v1 = S[k8 + 2 * j + 1][nl];
            bf16 h0 = __float2bfloat16(v0), h1 = __float2bfloat16(v1);
            hh[j] = __nv_bfloat162(h0, h1);
            ll[j] = __nv_bfloat162(__float2bfloat16(v0 - __bfloat162float(h0)),
                                   __float2bfloat16(v1 - __bfloat162float(h1)));
        }
        size_t o = (size_t)(n0 + nl) * Ks + k0 + k8;
        *(uint4*)&Th[o] = *(uint4*)hh;
        *(uint4*)&Tl[o] = *(uint4*)ll;
    }
}

// ---------------- HMMA split-K GEMM (mma.sync m16n8k16 bf16, 2-split) --------
// D[n 128][b 64] per CTA. 4 warps, warp w owns n rows [w*32, w*32+32).
// Tiles in smem at 80B row pitch (conflict-free ldmatrix, no XOR swizzle).
// NT slabs of BK=32 fully prefetched (one commit group per slab).
template<int NT>
__global__ __launch_bounds__(128)
void gemm_mma(int wsel, int nseg, int Kt, int Ntot) {
    extern __shared__ char smem[];
    constexpr int WSLAB = 128 * 80;   // 10240 B
    constexpr int XSLAB = 64 * 80;    // 5120 B
    const int WHo = 0;
    const int WLo = NT * WSLAB;
    const int XHo = 2 * NT * WSLAB;
    const int XLo = XHo + NT * XSLAB;
    uint32_t sb = smem_u32(smem);

    int tid = threadIdx.x, w = tid >> 5, lane = tid & 31;
    int n0 = blockIdx.x * 128;
    int kbeg = blockIdx.y * (NT * 32);

    const bf16 *Whp, *Wlp, *Xhp, *Xlp;
    if (wsel == 0)      { Whp = g_W1th; Wlp = g_W1tl; Xhp = g_X1h; Xlp = g_X1l; }
    else if (wsel == 1) { Whp = g_W2th; Wlp = g_W2tl; Xhp = g_X2h; Xlp = g_X2l; }
    else                { Whp = g_W3th; Wlp = g_W3tl; Xhp = g_X3h; Xlp = g_X3l; }
    if (nseg) {
        size_t xoff = (size_t)(n0 / nseg) * BB * Kt;
        Xhp += xoff; Xlp += xoff;
    }

    // --- prologue: stage all NT slabs, one commit group each ---
#pragma unroll
    for (int tt = 0; tt < NT; tt++) {
        int k0 = kbeg + tt * 32;
#pragma unroll
        for (int i = 0; i < 4; i++) {          // W: 128 rows x 4 chunks
            int q = tid + 128 * i;
            int r = q >> 2, c = q & 3;
            uint32_t doff = (uint32_t)(r * 80 + c * 16);
            const size_t so = (size_t)(n0 + r) * Kt + k0 + c * 8;
            cp16s(sb + WHo + tt * WSLAB + doff, Whp + so);
            cp16s(sb + WLo + tt * WSLAB + doff, Wlp + so);
        }
#pragma unroll
        for (int i = 0; i < 2; i++) {          // X: 64 rows x 4 chunks
            int q = tid + 128 * i;
            int r = q >> 2, c = q & 3;
            uint32_t doff = (uint32_t)(r * 80 + c * 16);
            const size_t so = (size_t)r * Kt + k0 + c * 8;
            cp16s(sb + XHo + tt * XSLAB + doff, Xhp + so);
            cp16s(sb + XLo + tt * XSLAB + doff, Xlp + so);
        }
        CP_COMMIT;
    }

    float d[2][8][4] = {};

    // per-lane ldmatrix source offsets (ldmatrix m8n8 lane-group convention)
    int rowA = (lane & 7) + ((lane >> 3) & 1) * 8;
    int cA = lane >> 4;
    uint32_t pA = (uint32_t)((w * 32 + rowA) * 80 + cA * 16);
    int rowX = (lane & 7) + (lane >> 4) * 8;
    int cX = (lane >> 3) & 1;
    uint32_t pB = (uint32_t)(rowX * 80 + cX * 16);

#pragma unroll
    for (int tt = 0; tt < NT; tt++) {
        cp_wait_n(NT - 1 - tt);
        __syncthreads();

#pragma unroll
        for (int s = 0; s < 2; s++) {          // two k16 steps per BK=32 slab
            uint32_t ko = s * 32;              // byte offset within 64B of data
            uint32_t ah[2][4], al[2][4];
            ldmat4(ah[0], sb + WHo + tt * WSLAB + pA + ko);
            ldmat4(ah[1], sb + WHo + tt * WSLAB + pA + ko + 16 * 80);
            ldmat4(al[0], sb + WLo + tt * WSLAB + pA + ko);
            ldmat4(al[1], sb + WLo + tt * WSLAB + pA + ko + 16 * 80);
            uint32_t bh[4][4], bl[4][4];
#pragma unroll
            for (int p = 0; p < 4; p++) {      // 4 x (16 b-rows)
                ldmat4(bh[p], sb + XHo + tt * XSLAB + pB + ko + p * 16 * 80);
                ldmat4(bl[p], sb + XLo + tt * XSLAB + pB + ko + p * 16 * 80);
            }
#pragma unroll
            for (int mt = 0; mt < 2; mt++)
#pragma unroll
                for (int nt = 0; nt < 8; nt++) {
                    int p = nt >> 1, hf = (nt & 1) * 2;
                    mma16816(d[mt][nt], ah[mt], bh[p][hf], bh[p][hf + 1]);
                    mma16816(d[mt][nt], ah[mt], bl[p][hf], bl[p][hf + 1]);
                    mma16816(d[mt][nt], al[mt], bh[p][hf], bh[p][hf + 1]);
                }
        }
    }

    // --- epilogue: P[(q*Ntot + n)*64 + b] ---
    float* pq = g_P + (size_t)blockIdx.y * Ntot * BB;
#pragma unroll
    for (int mt = 0; mt < 2; mt++)
#pragma unroll
        for (int nt = 0; nt < 8; nt++) {
            int n = n0 + w * 32 + mt * 16 + (lane >> 2);
            int b = nt * 8 + (lane & 3) * 2;
            *(float2*)&pq[(size_t)n * BB + b]       = make_float2(d[mt][nt][0], d[mt][nt][1]);
            *(float2*)&pq[(size_t)(n + 8) * BB + b] = make_float2(d[mt][nt][2], d[mt][nt][3]);
        }
}

// ---------------- transposing reduce: P[q][n][b] -> b-major output -----------
// ysel 0: -> g_X2 (bf16 hi/lo, bias=g_bcat), 1: -> g_X3 (bias), 2: -> g_h2 fp32
__global__ __launch_bounds__(256)
void reduceT(const float* __restrict__ bias, int ysel, int Ntot, int ks) {
    __shared__ float S[16][66];
    int n0 = blockIdx.x * 16;
    int t = threadIdx.x;
    int nl = t >> 4, b4 = t & 15;
    int n = n0 + nl;
    const float* p = g_P + (size_t)n * BB + b4 * 4;
    float4 s = *(const float4*)p;
    for (int q = 1; q < ks; q++) {
        float4 v = *(const float4*)(p + (size_t)q * Ntot * BB);
        s.x += v.x; s.y += v.y; s.z += v.z; s.w += v.w;
    }
    float bv = (ysel == 0) ? g_bcat[n] : bias[n];
    s.x += bv; s.y += bv; s.z += bv; s.w += bv;
    S[nl][b4 * 4 + 0] = s.x; S[nl][b4 * 4 + 1] = s.y;
    S[nl][b4 * 4 + 2] = s.z; S[nl][b4 * 4 + 3] = s.w;
    __syncthreads();

    int b = t >> 2, nn = (t & 3) * 4;
    float v0 = S[nn + 0][b], v1 = S[nn + 1][b], v2 = S[nn + 2][b], v3 = S[nn + 3][b];
    if (ysel == 2) {
        *(float4*)&g_h2[(size_t)b * Ntot + n0 + nn] = make_float4(v0, v1, v2, v3);
    } else {
        bf16* Yh = (ysel == 0) ? g_X2h : g_X3h;
        bf16* Yl = (ysel == 0) ? g_X2l : g_X3l;
        bf16 h0 = __float2bfloat16(v0), h1 = __float2bfloat16(v1);
        bf16 h2 = __float2bfloat16(v2), h3 = __float2bfloat16(v3);
        bf16 l0 = __float2bfloat16(v0 - __bfloat162float(h0));
        bf16 l1 = __float2bfloat16(v1 - __bfloat162float(h1));
        bf16 l2 = __float2bfloat16(v2 - __bfloat162float(h2));
        bf16 l3 = __float2bfloat16(v3 - __bfloat162float(h3));
        size_t o = (size_t)b * Ntot + n0 + nn;
        *(__nv_bfloat162*)&Yh[o]     = __nv_bfloat162(h0, h1);
        *(__nv_bfloat162*)&Yh[o + 2] = __nv_bfloat162(h2, h3);
        *(__nv_bfloat162*)&Yl[o]     = __nv_bfloat162(l0, l1);
        *(__nv_bfloat162*)&Yl[o + 2] = __nv_bfloat162(l2, l3);
    }
}

// ---------------- tiny output GEMM: h2[b][k] x Wout[1024,15] -----------------
__global__ void out_gemm(const float* __restrict__ Wout,
                         const float* __restrict__ bout,
                         float* __restrict__ out) {
    int n = blockIdx.x;   // 0..14
    int b = blockIdx.y;   // 0..63
    float s = 0.f;
    for (int k = threadIdx.x; k < HH; k += 128)
        s += g_h2[(size_t)b * HH + k] * Wout[(size_t)k * LL + n];
    __shared__ float red[4];
#pragma unroll
    for (int o = 16; o; o >>= 1) s += __shfl_down_sync(0xffffffffu, s, o);
    if ((threadIdx.x & 31) == 0) red[threadIdx.x >> 5] = s;
    __syncthreads();
    if (threadIdx.x == 0)
        out[b * LL + n] = red[0] + red[1] + red[2] + red[3] + bout[n];
}

// ---------------- launch ------------------------------------------------------
extern "C" void kernel_launch(void* const* d_in, const int* in_sizes, int n_in,
                              void* d_out, int out_size) {
    const float* x      = (const float*)d_in[0];
    const int*   eidx   = (const int*)d_in[1];
    const float* W_cls  = (const float*)d_in[2];
    const float* b_cls  = (const float*)d_in[3];
    const float* W_e1   = (const float*)d_in[4];
    const float* b_e1   = (const float*)d_in[5];
    const float* W_e2   = (const float*)d_in[6];
    const float* b_e2   = (const float*)d_in[7];
    const float* W1     = (const float*)d_in[8];
    const float* b1     = (const float*)d_in[9];
    const float* W2     = (const float*)d_in[10];
    const float* b2     = (const float*)d_in[11];
    const float* Wout   = (const float*)d_in[12];
    const float* bout   = (const float*)d_in[13];
    float* out = (float*)d_out;

    const int GSMEM = 2 * (2 * 128 * 80 + 2 * 64 * 80);  // NT=2: 61440 B
    cudaFuncSetAttribute(gemm_mma<2>, cudaFuncAttributeMaxDynamicSharedMemorySize,
                         GSMEM);

    // 1) prep + fused weight conversion (one launch)
    prep_kernel<<<dim3(BB, HH / 256), 256>>>(x, eidx, b_cls, b_e1, b_e2);
    convAll<<<1792, 256>>>(W_cls, W_e1, W_e2, W1, W2);

    // 2) GEMM1: block-diag(W_cls,W_e1,W_e2)^T x tanh-feats (24 x 16 CTAs, kchunk 64)
    gemm_mma<2><<<dim3(24, 16), 128, GSMEM>>>(0, HH, HH, 3 * HH);
    reduceT<<<3 * HH / 16, 256>>>(nullptr, 0, 3 * HH, 16);

    // 3) GEMM2: W1^T x H3 (8 x 48 CTAs, K=3072)
    gemm_mma<2><<<dim3(8, 48), 128, GSMEM>>>(1, 0, 3 * HH, HH);
    reduceT<<<HH / 16, 256>>>(b1, 1, HH, 48);

    // 4) GEMM3: W2^T x h1 (8 x 16 CTAs)
    gemm_mma<2><<<dim3(8, 16), 128, GSMEM>>>(2, 0, HH, HH);
    reduceT<<<HH / 16, 256>>>(b2, 2, HH, 16);

    // 5) output projection
    out_gemm<<<dim3(LL, BB), 128>>>(Wout, bout, out);

    (void)in_sizes; (void)n_in; (void)out_size;
}

// round 13
// speedup vs baseline: 1.7606x; 1.0448x over previous
#include <cuda_runtime.h>
#include <cuda_bf16.h>
#include <cstdint>

#define BB 64
#define HH 1024
#define SS 2048
#define LL 15

using bf16 = __nv_bfloat16;
typedef unsigned long long ull;

// ---------------- scratch (static device globals; no allocation) ------------
__device__ __align__(16) bf16 g_W1th[3*HH*HH], g_W1tl[3*HH*HH]; // [3072 n][1024 k]
__device__ __align__(16) bf16 g_W2th[HH*3*HH], g_W2tl[HH*3*HH]; // [1024 n][3072 k]
__device__ __align__(16) bf16 g_W3th[HH*HH],   g_W3tl[HH*HH];   // [1024][1024]
__device__ __align__(16) bf16 g_X1h[3*BB*HH],  g_X1l[3*BB*HH];  // [3 seg][64 b][1024 k]
__device__ __align__(16) bf16 g_X2h[BB*3*HH],  g_X2l[BB*3*HH];  // [64 b][3072 k]
__device__ __align__(16) bf16 g_X3h[BB*HH],    g_X3l[BB*HH];    // [64 b][1024 k]
__device__ __align__(16) float g_h2[BB*HH];                     // [64 b][1024 k]
__device__ __align__(16) float g_bcat[3*HH];
__device__ __align__(16) float g_P[16*3*HH*BB];                 // split-K partials [q][n][b]

// ---------------- PTX helpers ------------------------------------------------
__device__ __forceinline__ uint32_t smem_u32(const void* p) {
    uint32_t a;
    asm("{ .reg .u64 t; cvta.to.shared.u64 t, %1; cvt.u32.u64 %0, t; }" : "=r"(a) : "l"(p));
    return a;
}
__device__ __forceinline__ void cp16s(uint32_t saddr, const void* g) {
    asm volatile("cp.async.cg.shared.global [%0], [%1], 16;" :: "r"(saddr), "l"(g));
}
#define CP_COMMIT asm volatile("cp.async.commit_group;")
__device__ __forceinline__ void cp_wait_n(int n) {
    switch (n) {
        case 0: asm volatile("cp.async.wait_group 0;"); break;
        case 1: asm volatile("cp.async.wait_group 1;"); break;
        case 2: asm volatile("cp.async.wait_group 2;"); break;
        default: asm volatile("cp.async.wait_group 3;"); break;  // conservative for NT>4
    }
}
__device__ __forceinline__ void ldmat4(uint32_t (&r)[4], uint32_t addr) {
    asm volatile("ldmatrix.sync.aligned.m8n8.x4.shared.b16 {%0,%1,%2,%3}, [%4];"
                 : "=r"(r[0]), "=r"(r[1]), "=r"(r[2]), "=r"(r[3]) : "r"(addr));
}
__device__ __forceinline__ void mma16816(float (&d)[4], const uint32_t (&a)[4],
                                         uint32_t b0, uint32_t b1) {
    asm volatile("mma.sync.aligned.m16n8k16.row.col.f32.bf16.bf16.f32 "
                 "{%0,%1,%2,%3}, {%4,%5,%6,%7}, {%8,%9}, {%0,%1,%2,%3};"
                 : "+f"(d[0]), "+f"(d[1]), "+f"(d[2]), "+f"(d[3])
                 : "r"(a[0]), "r"(a[1]), "r"(a[2]), "r"(a[3]), "r"(b0), "r"(b1));
}

// ---------------- prep: span means + tanh + bf16 split ----------------------
__global__ void prep_kernel(const float* __restrict__ x,
                            const int* __restrict__ eidx,
                            const float* __restrict__ b_cls,
                            const float* __restrict__ b_e1,
                            const float* __restrict__ b_e2) {
    int b = blockIdx.x;
    int tid = threadIdx.x;  // 256
    int h = blockIdx.y * 256 + tid;

    if (blockIdx.y == 0 && b < 12) {
        int gidx = b * 256 + tid;
        if (gidx < HH)          g_bcat[gidx] = b_cls[gidx];
        else if (gidx < 2 * HH) g_bcat[gidx] = b_e1[gidx - HH];
        else                    g_bcat[gidx] = b_e2[gidx - 2 * HH];
    }

    int s1 = eidx[b * 4 + 0], e1 = eidx[b * 4 + 1];
    int s2 = eidx[b * 4 + 2], e2 = eidx[b * 4 + 3];
    float c1 = 1.0f / (float)max(e1 - s1, 1);
    float c2 = 1.0f / (float)max(e2 - s2, 1);
    const float* xb = x + (size_t)b * SS * HH;

    float a1 = 0.f;
    for (int p = s1; p < e1; ++p) a1 += xb[(size_t)p * HH + h];
    float a2 = 0.f;
    for (int p = s2; p < e2; ++p) a2 += xb[(size_t)p * HH + h];
    float v[3] = { tanhf(xb[h]), tanhf(a1 * c1), tanhf(a2 * c2) };
#pragma unroll
    for (int s = 0; s < 3; s++) {
        size_t idx = ((size_t)(s * BB + b)) * HH + h;
        bf16 hv = __float2bfloat16(v[s]);
        bf16 lv = __float2bfloat16(v[s] - __bfloat162float(hv));
        g_X1h[idx] = hv;
        g_X1l[idx] = lv;
    }
}

// ---------------- fused weight transpose + bf16 hi/lo split ------------------
__global__ __launch_bounds__(256)
void convAll(const float* __restrict__ Wc,  const float* __restrict__ We1,
             const float* __restrict__ We2, const float* __restrict__ W1,
             const float* __restrict__ W2) {
    __shared__ float S[64][65];
    int bid = blockIdx.x;
    const float* src; bf16 *Th, *Tl; int Ks; int base;
    if (bid < 256)       { src = Wc;  Th = g_W1th;                   Tl = g_W1tl;                   Ks = HH;   base = 0; }
    else if (bid < 512)  { src = We1; Th = g_W1th + (size_t)HH*HH;   Tl = g_W1tl + (size_t)HH*HH;   Ks = HH;   base = 256; }
    else if (bid < 768)  { src = We2; Th = g_W1th + (size_t)2*HH*HH; Tl = g_W1tl + (size_t)2*HH*HH; Ks = HH;   base = 512; }
    else if (bid < 1536) { src = W1;  Th = g_W2th;                   Tl = g_W2tl;                   Ks = 3*HH; base = 768; }
    else                 { src = W2;  Th = g_W3th;                   Tl = g_W3tl;                   Ks = HH;   base = 1536; }
    int tw = bid - base;
    int kt = tw >> 4, nt = tw & 15;
    int k0 = kt * 64, n0 = nt * 64;
    int t = threadIdx.x;

    int lr = t >> 4, lc = (t & 15) * 4;
#pragma unroll
    for (int i = 0; i < 4; i++) {
        float4 v = *(const float4*)(src + (size_t)(k0 + lr + 16 * i) * HH + n0 + lc);
        S[lr + 16 * i][lc + 0] = v.x; S[lr + 16 * i][lc + 1] = v.y;
        S[lr + 16 * i][lc + 2] = v.z; S[lr + 16 * i][lc + 3] = v.w;
    }
    __syncthreads();

    int k8 = (t & 7) * 8;
#pragma unroll
    for (int ii = 0; ii < 2; ii++) {
        int nl = (t >> 3) + 32 * ii;
        __nv_bfloat162 hh[4], ll[4];
#pragma unroll
        for (int j = 0; j < 4; j++) {
            float v0 = S[k8 + 2 * j][nl], v1 = S[k8 + 2 * j + 1][nl];
            bf16 h0 = __float2bfloat16(v0), h1 = __float2bfloat16(v1);
            hh[j] = __nv_bfloat162(h0, h1);
            ll[j] = __nv_bfloat162(__float2bfloat16(v0 - __bfloat162float(h0)),
                                   __float2bfloat16(v1 - __bfloat162float(h1)));
        }
        size_t o = (size_t)(n0 + nl) * Ks + k0 + k8;
        *(uint4*)&Th[o] = *(uint4*)hh;
        *(uint4*)&Tl[o] = *(uint4*)ll;
    }
}

// ---------------- HMMA split-K GEMM (mma.sync m16n8k16 bf16, 2-split) --------
template<int NT>
__global__ __launch_bounds__(128)
void gemm_mma(int wsel, int nseg, int Kt, int Ntot) {
    extern __shared__ char smem[];
    constexpr int WSLAB = 128 * 80;   // 10240 B
    constexpr int XSLAB = 64 * 80;    // 5120 B
    const int WHo = 0;
    const int WLo = NT * WSLAB;
    const int XHo = 2 * NT * WSLAB;
    const int XLo = XHo + NT * XSLAB;
    uint32_t sb = smem_u32(smem);

    int tid = threadIdx.x, w = tid >> 5, lane = tid & 31;
    int n0 = blockIdx.x * 128;
    int kbeg = blockIdx.y * (NT * 32);

    const bf16 *Whp, *Wlp, *Xhp, *Xlp;
    if (wsel == 0)      { Whp = g_W1th; Wlp = g_W1tl; Xhp = g_X1h; Xlp = g_X1l; }
    else if (wsel == 1) { Whp = g_W2th; Wlp = g_W2tl; Xhp = g_X2h; Xlp = g_X2l; }
    else                { Whp = g_W3th; Wlp = g_W3tl; Xhp = g_X3h; Xlp = g_X3l; }
    if (nseg) {
        size_t xoff = (size_t)(n0 / nseg) * BB * Kt;
        Xhp += xoff; Xlp += xoff;
    }

    // --- prologue: stage all NT slabs, one commit group each ---
#pragma unroll
    for (int tt = 0; tt < NT; tt++) {
        int k0 = kbeg + tt * 32;
#pragma unroll
        for (int i = 0; i < 4; i++) {          // W: 128 rows x 4 chunks
            int q = tid + 128 * i;
            int r = q >> 2, c = q & 3;
            uint32_t doff = (uint32_t)(r * 80 + c * 16);
            const size_t so = (size_t)(n0 + r) * Kt + k0 + c * 8;
            cp16s(sb + WHo + tt * WSLAB + doff, Whp + so);
            cp16s(sb + WLo + tt * WSLAB + doff, Wlp + so);
        }
#pragma unroll
        for (int i = 0; i < 2; i++) {          // X: 64 rows x 4 chunks
            int q = tid + 128 * i;
            int r = q >> 2, c = q & 3;
            uint32_t doff = (uint32_t)(r * 80 + c * 16);
            const size_t so = (size_t)r * Kt + k0 + c * 8;
            cp16s(sb + XHo + tt * XSLAB + doff, Xhp + so);
            cp16s(sb + XLo + tt * XSLAB + doff, Xlp + so);
        }
        CP_COMMIT;
    }

    float d[2][8][4] = {};

    int rowA = (lane & 7) + ((lane >> 3) & 1) * 8;
    int cA = lane >> 4;
    uint32_t pA = (uint32_t)((w * 32 + rowA) * 80 + cA * 16);
    int rowX = (lane & 7) + (lane >> 4) * 8;
    int cX = (lane >> 3) & 1;
    uint32_t pB = (uint32_t)(rowX * 80 + cX * 16);

#pragma unroll
    for (int tt = 0; tt < NT; tt++) {
        cp_wait_n(NT - 1 - tt);
        __syncthreads();

#pragma unroll
        for (int s = 0; s < 2; s++) {          // two k16 steps per BK=32 slab
            uint32_t ko = s * 32;
            uint32_t ah[2][4], al[2][4];
            ldmat4(ah[0], sb + WHo + tt * WSLAB + pA + ko);
            ldmat4(ah[1], sb + WHo + tt * WSLAB + pA + ko + 16 * 80);
            ldmat4(al[0], sb + WLo + tt * WSLAB + pA + ko);
            ldmat4(al[1], sb + WLo + tt * WSLAB + pA + ko + 16 * 80);
            uint32_t bh[4][4], bl[4][4];
#pragma unroll
            for (int p = 0; p < 4; p++) {
                ldmat4(bh[p], sb + XHo + tt * XSLAB + pB + ko + p * 16 * 80);
                ldmat4(bl[p], sb + XLo + tt * XSLAB + pB + ko + p * 16 * 80);
            }
#pragma unroll
            for (int mt = 0; mt < 2; mt++)
#pragma unroll
                for (int nt = 0; nt < 8; nt++) {
                    int p = nt >> 1, hf = (nt & 1) * 2;
                    mma16816(d[mt][nt], ah[mt], bh[p][hf], bh[p][hf + 1]);
                    mma16816(d[mt][nt], ah[mt], bl[p][hf], bl[p][hf + 1]);
                    mma16816(d[mt][nt], al[mt], bh[p][hf], bh[p][hf + 1]);
                }
        }
    }

    // --- epilogue: P[(q*Ntot + n)*64 + b] ---
    float* pq = g_P + (size_t)blockIdx.y * Ntot * BB;
#pragma unroll
    for (int mt = 0; mt < 2; mt++)
#pragma unroll
        for (int nt = 0; nt < 8; nt++) {
            int n = n0 + w * 32 + mt * 16 + (lane >> 2);
            int b = nt * 8 + (lane & 3) * 2;
            *(float2*)&pq[(size_t)n * BB + b]       = make_float2(d[mt][nt][0], d[mt][nt][1]);
            *(float2*)&pq[(size_t)(n + 8) * BB + b] = make_float2(d[mt][nt][2], d[mt][nt][3]);
        }
}

// ---------------- transposing reduce (compile-time KS, full-unroll MLP) ------
// ysel 0: -> g_X2 (bf16 hi/lo, bias=g_bcat), 1: -> g_X3 (bias), 2: -> g_h2 fp32
template<int KS>
__global__ __launch_bounds__(256)
void reduceT(const float* __restrict__ bias, int ysel, int Ntot) {
    __shared__ float S[16][66];
    int n0 = blockIdx.x * 16;
    int t = threadIdx.x;
    int nl = t >> 4, b4 = t & 15;
    int n = n0 + nl;
    const float* p = g_P + (size_t)n * BB + b4 * 4;
    float4 acc[KS];
#pragma unroll
    for (int q = 0; q < KS; q++)
        acc[q] = *(const float4*)(p + (size_t)q * Ntot * BB);
    float4 s = acc[0];
#pragma unroll
    for (int q = 1; q < KS; q++) {
        s.x += acc[q].x; s.y += acc[q].y; s.z += acc[q].z; s.w += acc[q].w;
    }
    float bv = (ysel == 0) ? g_bcat[n] : bias[n];
    s.x += bv; s.y += bv; s.z += bv; s.w += bv;
    S[nl][b4 * 4 + 0] = s.x; S[nl][b4 * 4 + 1] = s.y;
    S[nl][b4 * 4 + 2] = s.z; S[nl][b4 * 4 + 3] = s.w;
    __syncthreads();

    int b = t >> 2, nn = (t & 3) * 4;
    float v0 = S[nn + 0][b], v1 = S[nn + 1][b], v2 = S[nn + 2][b], v3 = S[nn + 3][b];
    if (ysel == 2) {
        *(float4*)&g_h2[(size_t)b * Ntot + n0 + nn] = make_float4(v0, v1, v2, v3);
    } else {
        bf16* Yh = (ysel == 0) ? g_X2h : g_X3h;
        bf16* Yl = (ysel == 0) ? g_X2l : g_X3l;
        bf16 h0 = __float2bfloat16(v0), h1 = __float2bfloat16(v1);
        bf16 h2 = __float2bfloat16(v2), h3 = __float2bfloat16(v3);
        bf16 l0 = __float2bfloat16(v0 - __bfloat162float(h0));
        bf16 l1 = __float2bfloat16(v1 - __bfloat162float(h1));
        bf16 l2 = __float2bfloat16(v2 - __bfloat162float(h2));
        bf16 l3 = __float2bfloat16(v3 - __bfloat162float(h3));
        size_t o = (size_t)b * Ntot + n0 + nn;
        *(__nv_bfloat162*)&Yh[o]     = __nv_bfloat162(h0, h1);
        *(__nv_bfloat162*)&Yh[o + 2] = __nv_bfloat162(h2, h3);
        *(__nv_bfloat162*)&Yl[o]     = __nv_bfloat162(l0, l1);
        *(__nv_bfloat162*)&Yl[o + 2] = __nv_bfloat162(l2, l3);
    }
}

// ---------------- tiny output GEMM: h2[b][k] x Wout[1024,15] -----------------
__global__ void out_gemm(const float* __restrict__ Wout,
                         const float* __restrict__ bout,
                         float* __restrict__ out) {
    int n = blockIdx.x;   // 0..14
    int b = blockIdx.y;   // 0..63
    float s = 0.f;
    for (int k = threadIdx.x; k < HH; k += 128)
        s += g_h2[(size_t)b * HH + k] * Wout[(size_t)k * LL + n];
    __shared__ float red[4];
#pragma unroll
    for (int o = 16; o; o >>= 1) s += __shfl_down_sync(0xffffffffu, s, o);
    if ((threadIdx.x & 31) == 0) red[threadIdx.x >> 5] = s;
    __syncthreads();
    if (threadIdx.x == 0)
        out[b * LL + n] = red[0] + red[1] + red[2] + red[3] + bout[n];
}

// ---------------- launch ------------------------------------------------------
extern "C" void kernel_launch(void* const* d_in, const int* in_sizes, int n_in,
                              void* d_out, int out_size) {
    const float* x      = (const float*)d_in[0];
    const int*   eidx   = (const int*)d_in[1];
    const float* W_cls  = (const float*)d_in[2];
    const float* b_cls  = (const float*)d_in[3];
    const float* W_e1   = (const float*)d_in[4];
    const float* b_e1   = (const float*)d_in[5];
    const float* W_e2   = (const float*)d_in[6];
    const float* b_e2   = (const float*)d_in[7];
    const float* W1     = (const float*)d_in[8];
    const float* b1     = (const float*)d_in[9];
    const float* W2     = (const float*)d_in[10];
    const float* b2     = (const float*)d_in[11];
    const float* Wout   = (const float*)d_in[12];
    const float* bout   = (const float*)d_in[13];
    float* out = (float*)d_out;

    const int SLAB = 2 * 128 * 80 + 2 * 64 * 80;   // 30720 B per K=32 slab
    cudaFuncSetAttribute(gemm_mma<4>, cudaFuncAttributeMaxDynamicSharedMemorySize,
                         4 * SLAB);                // 122880
    cudaFuncSetAttribute(gemm_mma<6>, cudaFuncAttributeMaxDynamicSharedMemorySize,
                         6 * SLAB);                // 184320

    // 1) prep + fused weight conversion
    prep_kernel<<<dim3(BB, HH / 256), 256>>>(x, eidx, b_cls, b_e1, b_e2);
    convAll<<<1792, 256>>>(W_cls, W_e1, W_e2, W1, W2);

    // 2) GEMM1: block-diag weights (24 x 8 CTAs, K=128/CTA)
    gemm_mma<4><<<dim3(24, 8), 128, 4 * SLAB>>>(0, HH, HH, 3 * HH);
    reduceT<8><<<3 * HH / 16, 256>>>(nullptr, 0, 3 * HH);

    // 3) GEMM2: W1^T x H3 (8 x 16 CTAs, K=192/CTA)
    gemm_mma<6><<<dim3(8, 16), 128, 6 * SLAB>>>(1, 0, 3 * HH, HH);
    reduceT<16><<<HH / 16, 256>>>(b1, 1, HH);

    // 4) GEMM3: W2^T x h1 (8 x 8 CTAs, K=128/CTA)
    gemm_mma<4><<<dim3(8, 8), 128, 4 * SLAB>>>(2, 0, HH, HH);
    reduceT<8><<<HH / 16, 256>>>(b2, 2, HH);

    // 5) output projection
    out_gemm<<<dim3(LL, BB), 128>>>(Wout, bout, out);

    (void)in_sizes; (void)n_in; (void)out_size;
}